// round 10
// baseline (speedup 1.0000x reference)
#include <cuda_runtime.h>
#include <cuda_bf16.h>
#include <math.h>
#include <float.h>
#include <stdint.h>

#define BB   8
#define NN   2048
#define DDIM 256
#define KNB  8
#define NNODE (BB*NN)         // 16384
#define NEDGE (NNODE*KNB)     // 131072
#define BN_EPS 1e-5f

// ---------------- scratch ----------------
__device__ float g_x[NNODE*DDIM];
__device__ __nv_bfloat16 g_xh[NNODE*DDIM];
__device__ __nv_bfloat16 g_xl[NNODE*DDIM];
__device__ float g_sq[NNODE];
__device__ int   g_nidx[NNODE*KNB];
__device__ float g_u[NNODE*DDIM];
__device__ float g_v[NNODE*DDIM];
__device__ float g_nmax[NNODE*DDIM];
__device__ float g_nmin[NNODE*DDIM];
__device__ float g_stats[4*DDIM];
__device__ float g_mv[4*DDIM];
__device__ float g_pmax[BB*8*DDIM];
__device__ __nv_bfloat16 g_w1t_h[512*DDIM];
__device__ __nv_bfloat16 g_w1t_l[512*DDIM];
__device__ __nv_bfloat16 g_w2t_h[DDIM*DDIM];
__device__ __nv_bfloat16 g_w2t_l[DDIM*DDIM];

// ---------------- scalar helpers ----------------
__device__ __forceinline__ unsigned long long pack2(float lo, float hi) {
    unsigned long long r;
    asm("mov.b64 %0, {%1, %2};" : "=l"(r) : "f"(lo), "f"(hi));
    return r;
}
__device__ __forceinline__ void unpack2(unsigned long long v, float& lo, float& hi) {
    asm("mov.b64 {%0, %1}, %2;" : "=f"(lo), "=f"(hi) : "l"(v));
}
__device__ __forceinline__ void ffma2(unsigned long long& d, unsigned long long a, unsigned long long b) {
    asm("fma.rn.f32x2 %0, %1, %2, %0;" : "+l"(d) : "l"(a), "l"(b));
}
__device__ __forceinline__ float wredsum(float s) {
#pragma unroll
    for (int o = 16; o; o >>= 1) s += __shfl_xor_sync(0xffffffffu, s, o);
    return s;
}
__device__ __forceinline__ bool dless(float d1, int i1, float d2, int i2) {
    return d1 < d2 || (d1 == d2 && i1 < i2);
}
__device__ __forceinline__ void mma16816(float* c, uint32_t a0, uint32_t a1, uint32_t a2, uint32_t a3,
                                         uint32_t b0, uint32_t b1) {
    asm volatile(
        "mma.sync.aligned.m16n8k16.row.col.f32.bf16.bf16.f32 "
        "{%0,%1,%2,%3}, {%4,%5,%6,%7}, {%8,%9}, {%0,%1,%2,%3};"
        : "+f"(c[0]), "+f"(c[1]), "+f"(c[2]), "+f"(c[3])
        : "r"(a0), "r"(a1), "r"(a2), "r"(a3), "r"(b0), "r"(b1));
}
__device__ __forceinline__ void ldsm_x4(uint32_t& r0, uint32_t& r1, uint32_t& r2, uint32_t& r3, uint32_t addr) {
    asm volatile("ldmatrix.sync.aligned.m8n8.x4.shared.b16 {%0,%1,%2,%3}, [%4];"
        : "=r"(r0), "=r"(r1), "=r"(r2), "=r"(r3) : "r"(addr));
}
__device__ __forceinline__ uint32_t smem_u32p(const void* p) {
    return (uint32_t)__cvta_generic_to_shared(p);
}
__device__ __forceinline__ void bf16split(float v, __nv_bfloat16& h, __nv_bfloat16& l) {
    h = __float2bfloat16(v);
    l = __float2bfloat16(v - __bfloat162float(h));
}

// ---------------- K1: point features + merge GEMM ----------------
__global__ void __launch_bounds__(256) k1_features(
    const int*   __restrict__ class_idx, const float* __restrict__ colors,
    const float* __restrict__ positions, const float* __restrict__ class_table,
    const float* __restrict__ posW1, const float* __restrict__ posb1,
    const float* __restrict__ posW2, const float* __restrict__ posb2,
    const float* __restrict__ colW1, const float* __restrict__ colb1,
    const float* __restrict__ colW2, const float* __restrict__ colb2,
    const float* __restrict__ mW,    const float* __restrict__ mb)
{
    __shared__ __align__(16) float fs[768*16];
    int tid = threadIdx.x, lane = tid & 31, w = tid >> 5;
    int g0 = blockIdx.x * 16;

    if (blockIdx.x == 0)
        for (int i = tid; i < 4*DDIM; i += 256) g_stats[i] = 0.f;

    for (int pp = 0; pp < 2; pp++) {
        int p = w*2 + pp;
        int g = g0 + p;
        int cls = class_idx[g];
        float v[8]; float s = 0.f;
#pragma unroll
        for (int t = 0; t < 8; t++) { v[t] = class_table[cls*DDIM + lane + 32*t]; s += v[t]*v[t]; }
        s = wredsum(s);
        float sc = 1.f / fmaxf(sqrtf(s), 1e-12f);
#pragma unroll
        for (int t = 0; t < 8; t++) fs[(lane + 32*t)*16 + p] = v[t]*sc;

        float a0 = colors[g*3+0], a1 = colors[g*3+1], a2 = colors[g*3+2];
        float h = fmaxf(colb1[lane] + a0*colW1[lane] + a1*colW1[32+lane] + a2*colW1[64+lane], 0.f);
#pragma unroll
        for (int t = 0; t < 8; t++) v[t] = colb2[lane + 32*t];
#pragma unroll 8
        for (int k = 0; k < 32; k++) {
            float hk = __shfl_sync(0xffffffffu, h, k);
#pragma unroll
            for (int t = 0; t < 8; t++) v[t] += hk * colW2[k*DDIM + lane + 32*t];
        }
        s = 0.f;
#pragma unroll
        for (int t = 0; t < 8; t++) { v[t] = fmaxf(v[t], 0.f); s += v[t]*v[t]; }
        s = wredsum(s);
        sc = 1.f / fmaxf(sqrtf(s), 1e-12f);
#pragma unroll
        for (int t = 0; t < 8; t++) fs[(256 + lane + 32*t)*16 + p] = v[t]*sc;

        a0 = positions[g*3+0]; a1 = positions[g*3+1]; a2 = positions[g*3+2];
        h = fmaxf(posb1[lane] + a0*posW1[lane] + a1*posW1[32+lane] + a2*posW1[64+lane], 0.f);
#pragma unroll
        for (int t = 0; t < 8; t++) v[t] = posb2[lane + 32*t];
#pragma unroll 8
        for (int k = 0; k < 32; k++) {
            float hk = __shfl_sync(0xffffffffu, h, k);
#pragma unroll
            for (int t = 0; t < 8; t++) v[t] += hk * posW2[k*DDIM + lane + 32*t];
        }
        s = 0.f;
#pragma unroll
        for (int t = 0; t < 8; t++) { v[t] = fmaxf(v[t], 0.f); s += v[t]*v[t]; }
        s = wredsum(s);
        sc = 1.f / fmaxf(sqrtf(s), 1e-12f);
#pragma unroll
        for (int t = 0; t < 8; t++) fs[(512 + lane + 32*t)*16 + p] = v[t]*sc;
    }
    __syncthreads();

    int d = tid;
    float bv = mb[d];
    unsigned long long acc[8];
    unsigned long long bi = pack2(bv, bv);
#pragma unroll
    for (int q = 0; q < 8; q++) acc[q] = bi;
    for (int c = 0; c < 768; c++) {
        float wv = mW[c*DDIM + d];
        unsigned long long w2 = pack2(wv, wv);
        const ulonglong2* f2 = (const ulonglong2*)&fs[c*16];
#pragma unroll
        for (int q = 0; q < 4; q++) {
            ulonglong2 u = f2[q];
            ffma2(acc[2*q],   w2, u.x);
            ffma2(acc[2*q+1], w2, u.y);
        }
    }
    __syncthreads();
    if (tid < 16) fs[tid] = 0.f;
    __syncthreads();
    float xv[16];
#pragma unroll
    for (int q = 0; q < 8; q++) {
        float v0, v1; unpack2(acc[q], v0, v1);
        v0 = fmaxf(v0, 0.f); v1 = fmaxf(v1, 0.f);
        g_x[(g0 + 2*q  )*DDIM + d] = v0;
        g_x[(g0 + 2*q+1)*DDIM + d] = v1;
        xv[2*q] = v0*v0; xv[2*q+1] = v1*v1;
    }
#pragma unroll
    for (int p = 0; p < 16; p++) {
        float s = wredsum(xv[p]);
        if (lane == 0) atomicAdd(&fs[p], s);
    }
    __syncthreads();
    if (tid < 16) g_sq[g0 + tid] = fs[tid];
}

// ---------------- K1b: split x into bf16 hi/lo ----------------
__global__ void __launch_bounds__(256) k1b_split()
{
    int i = (blockIdx.x*256 + threadIdx.x)*4;
    float4 v = *(const float4*)&g_x[i];
    __nv_bfloat16 h0, h1, h2, h3, l0, l1, l2, l3;
    bf16split(v.x, h0, l0); bf16split(v.y, h1, l1);
    bf16split(v.z, h2, l2); bf16split(v.w, h3, l3);
    __nv_bfloat162 hp0; hp0.x = h0; hp0.y = h1;
    __nv_bfloat162 hp1; hp1.x = h2; hp1.y = h3;
    __nv_bfloat162 lp0; lp0.x = l0; lp0.y = l1;
    __nv_bfloat162 lp1; lp1.x = l2; lp1.y = l3;
    *(__nv_bfloat162*)&g_xh[i]     = hp0;
    *(__nv_bfloat162*)&g_xh[i + 2] = hp1;
    *(__nv_bfloat162*)&g_xl[i]     = lp0;
    *(__nv_bfloat162*)&g_xl[i + 2] = lp1;
}

// ---------------- K_prep: transposed bf16 hi/lo weight tables ----------------
__global__ void __launch_bounds__(256) k_prep(const float* __restrict__ W1, const float* __restrict__ W2)
{
    int idx = blockIdx.x*256 + threadIdx.x;
    if (idx < 512*DDIM) {
        int n = idx >> 8, k = idx & 255;
        float val = (n < DDIM) ? (W1[k*DDIM + n] - W1[(k+DDIM)*DDIM + n])
                               : W1[(k+DDIM)*DDIM + (n - DDIM)];
        __nv_bfloat16 h, l; bf16split(val, h, l);
        g_w1t_h[idx] = h; g_w1t_l[idx] = l;
    } else {
        int i2 = idx - 512*DDIM;
        int n = i2 >> 8, k = i2 & 255;
        float val = W2[k*DDIM + n];
        __nv_bfloat16 h, l; bf16split(val, h, l);
        g_w2t_h[i2] = h; g_w2t_l[i2] = l;
    }
}

// ---------------- K2: HMMA bf16-split gram + fused top-8 (ldmatrix fragments) ----------------
#define K2_SMEM_SZ 109312
__global__ void __launch_bounds__(256) k2_mma()
{
    extern __shared__ __align__(16) char sm[];
    float* sq_i_s = (float*)(sm + 0);
    float* sq_j_s = (float*)(sm + 256);
    float* topd   = (float*)(sm + 768);
    int*   topi   = (int*)(sm + 2816);
    __nv_bfloat16* Ah = (__nv_bfloat16*)(sm + 4864);
    __nv_bfloat16* Al = (__nv_bfloat16*)(sm + 38656);
    __nv_bfloat16* Bh = (__nv_bfloat16*)(sm + 72448);
    __nv_bfloat16* Bl = (__nv_bfloat16*)(sm + 90880);
    float* dist = (float*)(sm + 72448);

    int tid = threadIdx.x, lane = tid & 31, w = tid >> 5;
    int b = blockIdx.y;
    int i0 = blockIdx.x * 64;
    int nb = b*NN;

    for (int s = tid; s < 512; s += 256) { topd[s] = FLT_MAX; topi[s] = 0x7fffffff; }
    if (tid < 64) sq_i_s[tid] = g_sq[nb + i0 + tid];

    for (int s = tid; s < 64*32; s += 256) {
        int r = s >> 5, kq = (s & 31) * 8;
        int gofs = (nb + i0 + r)*DDIM + kq;
        *(uint4*)&Ah[r*264 + kq] = *(const uint4*)&g_xh[gofs];
        *(uint4*)&Al[r*264 + kq] = *(const uint4*)&g_xl[gofs];
    }
    __syncthreads();

    int wm = w & 3, wn = w >> 2;
    int m0 = wm*16;
    int arow = lane >> 2;
    int kq2  = (lane & 3) * 2;
    int grp = lane >> 3, r8 = lane & 7;

    // ldmatrix lane base offsets (bytes)
    // A tiles: row add (grp&1)*8, k add (grp>>1)*8
    uint32_t aoff = (uint32_t)(((m0 + (grp&1)*8 + r8)*264 + (grp>>1)*8) * 2);
    uint32_t AhB = smem_u32p(Ah) + aoff;
    uint32_t AlB = smem_u32p(Al) + aoff;
    // B tiles: row add (grp>>1)*8, k add (grp&1)*8; pair p adds 16 rows
    uint32_t boff = (uint32_t)(((wn*64 + (grp>>1)*8 + r8)*72 + (grp&1)*8) * 2);
    uint32_t BhB = smem_u32p(Bh) + boff;
    uint32_t BlB = smem_u32p(Bl) + boff;

    float c[8][4];
#pragma unroll
    for (int nt = 0; nt < 8; nt++)
#pragma unroll
        for (int q = 0; q < 4; q++) c[nt][q] = 0.f;

    for (int jc = 0; jc < 16; jc++) {
        int j0 = jc * 128;
        if (tid < 128) sq_j_s[tid] = g_sq[nb + j0 + tid];

        for (int ks = 0; ks < 4; ks++) {
            for (int s = tid; s < 128*8; s += 256) {
                int r = s >> 3, kq = (s & 7) * 8;
                int gofs = (nb + j0 + r)*DDIM + ks*64 + kq;
                *(uint4*)&Bh[r*72 + kq] = *(const uint4*)&g_xh[gofs];
                *(uint4*)&Bl[r*72 + kq] = *(const uint4*)&g_xl[gofs];
            }
            __syncthreads();
#pragma unroll
            for (int k0 = 0; k0 < 64; k0 += 16) {
                uint32_t ka = (uint32_t)((ks*64 + k0) * 2);
                uint32_t kb = (uint32_t)(k0 * 2);
                uint32_t ah0, ah1, ah2, ah3, al0, al1, al2, al3;
                ldsm_x4(ah0, ah1, ah2, ah3, AhB + ka);
                ldsm_x4(al0, al1, al2, al3, AlB + ka);
#pragma unroll
                for (int p = 0; p < 4; p++) {
                    uint32_t bh0, bh1, bh2, bh3, bl0, bl1, bl2, bl3;
                    ldsm_x4(bh0, bh1, bh2, bh3, BhB + (uint32_t)(p*16*72*2) + kb);
                    ldsm_x4(bl0, bl1, bl2, bl3, BlB + (uint32_t)(p*16*72*2) + kb);
                    mma16816(c[2*p],   ah0, ah1, ah2, ah3, bh0, bh1);
                    mma16816(c[2*p],   ah0, ah1, ah2, ah3, bl0, bl1);
                    mma16816(c[2*p],   al0, al1, al2, al3, bh0, bh1);
                    mma16816(c[2*p+1], ah0, ah1, ah2, ah3, bh2, bh3);
                    mma16816(c[2*p+1], ah0, ah1, ah2, ah3, bl2, bl3);
                    mma16816(c[2*p+1], al0, al1, al2, al3, bh2, bh3);
                }
            }
            __syncthreads();
        }

        float sqi0 = sq_i_s[m0 + arow];
        float sqi1 = sq_i_s[m0 + arow + 8];
#pragma unroll
        for (int nt = 0; nt < 8; nt++) {
            int colj = wn*64 + nt*8 + kq2;
            float sj0 = sq_j_s[colj], sj1 = sq_j_s[colj + 1];
            float2 o0 = { sqi0 + sj0 - 2.f*c[nt][0], sqi0 + sj1 - 2.f*c[nt][1] };
            float2 o1 = { sqi1 + sj0 - 2.f*c[nt][2], sqi1 + sj1 - 2.f*c[nt][3] };
            *(float2*)&dist[(m0 + arow    )*132 + colj] = o0;
            *(float2*)&dist[(m0 + arow + 8)*132 + colj] = o1;
        }
        __syncthreads();
        for (int rr = 0; rr < 8; rr++) {
            int row = w*8 + rr;
#pragma unroll
            for (int ps = 0; ps < 4; ps++) {
                float cd = dist[row*132 + ps*32 + lane];
                int   cj = j0 + ps*32 + lane;
                float thr_d = topd[row*8+7]; int thr_i = topi[row*8+7];
                bool pass = dless(cd, cj, thr_d, thr_i);
                unsigned m = __ballot_sync(0xffffffffu, pass);
                while (m) {
                    int src = __ffs(m) - 1; m &= m - 1;
                    float id = __shfl_sync(0xffffffffu, cd, src);
                    int   ij = __shfl_sync(0xffffffffu, cj, src);
                    if (lane == 0) {
                        if (dless(id, ij, topd[row*8+7], topi[row*8+7])) {
                            int p = 7;
                            while (p > 0 && dless(id, ij, topd[row*8+p-1], topi[row*8+p-1])) {
                                topd[row*8+p] = topd[row*8+p-1];
                                topi[row*8+p] = topi[row*8+p-1];
                                p--;
                            }
                            topd[row*8+p] = id; topi[row*8+p] = ij;
                        }
                    }
                }
                __syncwarp();
            }
        }
        __syncthreads();
#pragma unroll
        for (int nt = 0; nt < 8; nt++)
#pragma unroll
            for (int q = 0; q < 4; q++) c[nt][q] = 0.f;
    }

    for (int s = tid; s < 512; s += 256)
        g_nidx[(nb + i0 + (s >> 3))*KNB + (s & 7)] = topi[s];
}

// ---------------- K3a: HMMA u/v GEMM (ldmatrix fragments) ----------------
#define K3A_SMEM_SZ 73728
__global__ void __launch_bounds__(256) k3a_mma(const float* __restrict__ b1)
{
    extern __shared__ __align__(16) char sm3[];
    __nv_bfloat16* Ah = (__nv_bfloat16*)(sm3 + 0);
    __nv_bfloat16* Al = (__nv_bfloat16*)(sm3 + 18432);
    __nv_bfloat16* Wh = (__nv_bfloat16*)(sm3 + 36864);
    __nv_bfloat16* Wl = (__nv_bfloat16*)(sm3 + 55296);

    int tid = threadIdx.x, lane = tid & 31, w = tid >> 5;
    int cg = blockIdx.x;
    int r0 = blockIdx.y * 128;
    int m0 = w*16;
    int arow = lane >> 2;
    int kq2  = (lane & 3) * 2;
    int grp = lane >> 3, r8 = lane & 7;

    uint32_t aoff = (uint32_t)(((m0 + (grp&1)*8 + r8)*72 + (grp>>1)*8) * 2);
    uint32_t AhB = smem_u32p(Ah) + aoff;
    uint32_t AlB = smem_u32p(Al) + aoff;
    uint32_t boff = (uint32_t)((((grp>>1)*8 + r8)*72 + (grp&1)*8) * 2);
    uint32_t WhB = smem_u32p(Wh) + boff;
    uint32_t WlB = smem_u32p(Wl) + boff;

    float c[16][4];
#pragma unroll
    for (int nt = 0; nt < 16; nt++)
#pragma unroll
        for (int q = 0; q < 4; q++) c[nt][q] = 0.f;

    for (int ks = 0; ks < 4; ks++) {
        for (int s = tid; s < 1024; s += 256) {
            int r = s >> 3, kq = (s & 7) * 8;
            int gofs = (r0 + r)*DDIM + ks*64 + kq;
            *(uint4*)&Ah[r*72 + kq] = *(const uint4*)&g_xh[gofs];
            *(uint4*)&Al[r*72 + kq] = *(const uint4*)&g_xl[gofs];
        }
        for (int s = tid; s < 1024; s += 256) {
            int n = s >> 3, kq = (s & 7) * 8;
            int gofs = (cg*128 + n)*DDIM + ks*64 + kq;
            *(uint4*)&Wh[n*72 + kq] = *(const uint4*)&g_w1t_h[gofs];
            *(uint4*)&Wl[n*72 + kq] = *(const uint4*)&g_w1t_l[gofs];
        }
        __syncthreads();
#pragma unroll
        for (int k0 = 0; k0 < 64; k0 += 16) {
            uint32_t kb = (uint32_t)(k0 * 2);
            uint32_t ah0, ah1, ah2, ah3, al0, al1, al2, al3;
            ldsm_x4(ah0, ah1, ah2, ah3, AhB + kb);
            ldsm_x4(al0, al1, al2, al3, AlB + kb);
#pragma unroll
            for (int p = 0; p < 8; p++) {
                uint32_t bh0, bh1, bh2, bh3, bl0, bl1, bl2, bl3;
                ldsm_x4(bh0, bh1, bh2, bh3, WhB + (uint32_t)(p*16*72*2) + kb);
                ldsm_x4(bl0, bl1, bl2, bl3, WlB + (uint32_t)(p*16*72*2) + kb);
                mma16816(c[2*p],   ah0, ah1, ah2, ah3, bh0, bh1);
                mma16816(c[2*p],   ah0, ah1, ah2, ah3, bl0, bl1);
                mma16816(c[2*p],   al0, al1, al2, al3, bh0, bh1);
                mma16816(c[2*p+1], ah0, ah1, ah2, ah3, bh2, bh3);
                mma16816(c[2*p+1], ah0, ah1, ah2, ah3, bl2, bl3);
                mma16816(c[2*p+1], al0, al1, al2, al3, bh2, bh3);
            }
        }
        __syncthreads();
    }

    bool isU = (cg < 2);
    int row0 = r0 + m0 + arow;
#pragma unroll
    for (int nt = 0; nt < 16; nt++) {
        int gcol = (cg & 1)*128 + nt*8 + kq2;
        if (isU) {
            float b0 = b1[gcol], bb1 = b1[gcol+1];
            g_u[row0*DDIM + gcol]       = c[nt][0] + b0;
            g_u[row0*DDIM + gcol + 1]   = c[nt][1] + bb1;
            g_u[(row0+8)*DDIM + gcol]   = c[nt][2] + b0;
            g_u[(row0+8)*DDIM + gcol+1] = c[nt][3] + bb1;
        } else {
            g_v[row0*DDIM + gcol]       = c[nt][0];
            g_v[row0*DDIM + gcol + 1]   = c[nt][1];
            g_v[(row0+8)*DDIM + gcol]   = c[nt][2];
            g_v[(row0+8)*DDIM + gcol+1] = c[nt][3];
        }
    }
}

// ---------------- K3b: BN1 stats over all edges ----------------
__global__ void __launch_bounds__(256) k3b_stats()
{
    __shared__ int jn[128];
    int tid = threadIdx.x;
    int node0 = blockIdx.x * 16;
    if (tid < 128) jn[tid] = g_nidx[node0*KNB + tid];
    __syncthreads();
    int d = tid;
    float s = 0.f, s2 = 0.f;
#pragma unroll 4
    for (int n = 0; n < 16; n++) {
        float un = g_u[(node0 + n)*DDIM + d];
#pragma unroll
        for (int k = 0; k < 8; k++) {
            int b = (node0 + n) >> 11;
            int j = b*NN + jn[n*8 + k];
            float hv = fmaxf(un + g_v[j*DDIM + d], 0.f);
            s += hv; s2 += hv*hv;
        }
    }
    atomicAdd(&g_stats[d], s);
    atomicAdd(&g_stats[DDIM + d], s2);
}

// ---------------- finalize BN stats ----------------
__global__ void k_finalize(int si, int mo, const float* __restrict__ gamma, const float* __restrict__ beta)
{
    int d = threadIdx.x;
    float inv = 1.f / (float)NEDGE;
    float m = g_stats[si + d] * inv;
    float v = g_stats[si + DDIM + d] * inv - m*m;
    float rstd = rsqrtf(v + BN_EPS);
    float sc = rstd * gamma[d];
    g_mv[mo + d] = sc;
    g_mv[mo + DDIM + d] = beta[d] - m*sc;
}

// ---------------- K4: HMMA edge GEMM2 (ldmatrix fragments) ----------------
#define K4_SMEM_SZ 94464
__global__ void __launch_bounds__(256) k4_mma(const float* __restrict__ b2)
{
    extern __shared__ __align__(16) char sm4[];
    __nv_bfloat16* Wh = (__nv_bfloat16*)(sm4 + 0);
    __nv_bfloat16* Wl = (__nv_bfloat16*)(sm4 + 36864);
    __nv_bfloat16* Eh = (__nv_bfloat16*)(sm4 + 73728);
    __nv_bfloat16* El = (__nv_bfloat16*)(sm4 + 82944);
    int*   jn  = (int*)(sm4 + 92160);
    float* mvs = (float*)(sm4 + 92416);
    float* Cs  = (float*)(sm4 + 0);

    int tid = threadIdx.x, lane = tid & 31, w = tid >> 5;
    int wm = w & 3, wn = w >> 2;
    int m0 = wm*16;
    int arow = lane >> 2;
    int kq2  = (lane & 3) * 2;
    int grp = lane >> 3, r8 = lane & 7;
    int node0 = blockIdx.x * 8;
    int bofs = (node0 >> 11) * NN;

    if (tid < 64) jn[tid] = g_nidx[node0*KNB + tid];
    for (int s = tid; s < 512; s += 256) mvs[s] = g_mv[s];
    __syncthreads();

    uint32_t aoff = (uint32_t)(((m0 + (grp&1)*8 + r8)*72 + (grp>>1)*8) * 2);
    uint32_t EhB = smem_u32p(Eh) + aoff;
    uint32_t ElB = smem_u32p(El) + aoff;
    uint32_t boff = (uint32_t)(((wn*128 + (grp>>1)*8 + r8)*72 + (grp&1)*8) * 2);
    uint32_t WhB = smem_u32p(Wh) + boff;
    uint32_t WlB = smem_u32p(Wl) + boff;

    float c[16][4];
#pragma unroll
    for (int nt = 0; nt < 16; nt++)
#pragma unroll
        for (int q = 0; q < 4; q++) c[nt][q] = 0.f;

    int e_ = tid >> 2;
    int kq16 = (tid & 3) * 16;
    int enode = node0 + (e_ >> 3);
    int ej = bofs + jn[e_];

    for (int ks = 0; ks < 4; ks++) {
        for (int s = tid; s < 2048; s += 256) {
            int n = s >> 3, kq = (s & 7) * 8;
            int gofs = n*DDIM + ks*64 + kq;
            *(uint4*)&Wh[n*72 + kq] = *(const uint4*)&g_w2t_h[gofs];
            *(uint4*)&Wl[n*72 + kq] = *(const uint4*)&g_w2t_l[gofs];
        }
#pragma unroll
        for (int t = 0; t < 4; t++) {
            int kl = ks*64 + kq16 + t*4;
            float4 uu = *(const float4*)&g_u[enode*DDIM + kl];
            float4 vv = *(const float4*)&g_v[ej*DDIM + kl];
            float h0 = fmaxf(uu.x + vv.x, 0.f)*mvs[kl+0] + mvs[DDIM+kl+0];
            float h1 = fmaxf(uu.y + vv.y, 0.f)*mvs[kl+1] + mvs[DDIM+kl+1];
            float h2 = fmaxf(uu.z + vv.z, 0.f)*mvs[kl+2] + mvs[DDIM+kl+2];
            float h3 = fmaxf(uu.w + vv.w, 0.f)*mvs[kl+3] + mvs[DDIM+kl+3];
            __nv_bfloat16 hh0,hh1,hh2,hh3,ll0,ll1,ll2,ll3;
            bf16split(h0,hh0,ll0); bf16split(h1,hh1,ll1);
            bf16split(h2,hh2,ll2); bf16split(h3,hh3,ll3);
            __nv_bfloat162 ph0; ph0.x=hh0; ph0.y=hh1;
            __nv_bfloat162 ph1; ph1.x=hh2; ph1.y=hh3;
            __nv_bfloat162 pl0; pl0.x=ll0; pl0.y=ll1;
            __nv_bfloat162 pl1; pl1.x=ll2; pl1.y=ll3;
            int eo = e_*72 + kq16 + t*4;
            *(__nv_bfloat162*)&Eh[eo]   = ph0;
            *(__nv_bfloat162*)&Eh[eo+2] = ph1;
            *(__nv_bfloat162*)&El[eo]   = pl0;
            *(__nv_bfloat162*)&El[eo+2] = pl1;
        }
        __syncthreads();
#pragma unroll
        for (int k0 = 0; k0 < 64; k0 += 16) {
            uint32_t kb = (uint32_t)(k0 * 2);
            uint32_t ah0, ah1, ah2, ah3, al0, al1, al2, al3;
            ldsm_x4(ah0, ah1, ah2, ah3, EhB + kb);
            ldsm_x4(al0, al1, al2, al3, ElB + kb);
#pragma unroll
            for (int p = 0; p < 8; p++) {
                uint32_t bh0, bh1, bh2, bh3, bl0, bl1, bl2, bl3;
                ldsm_x4(bh0, bh1, bh2, bh3, WhB + (uint32_t)(p*16*72*2) + kb);
                ldsm_x4(bl0, bl1, bl2, bl3, WlB + (uint32_t)(p*16*72*2) + kb);
                mma16816(c[2*p],   ah0, ah1, ah2, ah3, bh0, bh1);
                mma16816(c[2*p],   ah0, ah1, ah2, ah3, bl0, bl1);
                mma16816(c[2*p],   al0, al1, al2, al3, bh0, bh1);
                mma16816(c[2*p+1], ah0, ah1, ah2, ah3, bh2, bh3);
                mma16816(c[2*p+1], ah0, ah1, ah2, ah3, bl2, bl3);
                mma16816(c[2*p+1], al0, al1, al2, al3, bh2, bh3);
            }
        }
        __syncthreads();
    }

#pragma unroll
    for (int nt = 0; nt < 16; nt++) {
        int col = wn*128 + nt*8 + kq2;
        float b0 = b2[col], bb1 = b2[col+1];
        Cs[(m0+arow  )*260 + col]     = fmaxf(c[nt][0] + b0, 0.f);
        Cs[(m0+arow  )*260 + col + 1] = fmaxf(c[nt][1] + bb1, 0.f);
        Cs[(m0+arow+8)*260 + col]     = fmaxf(c[nt][2] + b0, 0.f);
        Cs[(m0+arow+8)*260 + col + 1] = fmaxf(c[nt][3] + bb1, 0.f);
    }
    __syncthreads();

    int d = tid;
    float ts = 0.f, tq = 0.f;
#pragma unroll
    for (int nd = 0; nd < 8; nd++) {
        float mx = -FLT_MAX, mn = FLT_MAX;
#pragma unroll
        for (int e2 = 0; e2 < 8; e2++) {
            float vv = Cs[(nd*8 + e2)*260 + d];
            mx = fmaxf(mx, vv); mn = fminf(mn, vv);
            ts += vv; tq += vv*vv;
        }
        g_nmax[(node0 + nd)*DDIM + d] = mx;
        g_nmin[(node0 + nd)*DDIM + d] = mn;
    }
    atomicAdd(&g_stats[2*DDIM + d], ts);
    atomicAdd(&g_stats[3*DDIM + d], tq);
}

// ---------------- K5: bn2-apply on node extrema + partial max ----------------
__global__ void __launch_bounds__(256) k5_maxpart()
{
    int b = blockIdx.y;
    int ch = blockIdx.x;
    int d = threadIdx.x;
    float sc = g_mv[2*DDIM + d], sh = g_mv[3*DDIM + d];
    const float* src = (sc > 0.f) ? g_nmax : g_nmin;
    int base = b*NN + ch*256;
    float m = -FLT_MAX;
    for (int n = 0; n < 256; n++)
        m = fmaxf(m, src[(base + n)*DDIM + d]);
    g_pmax[(b*8 + ch)*DDIM + d] = m*sc + sh;
}

// ---------------- K6: final max + head MLP + l2norm ----------------
__global__ void __launch_bounds__(256) k6_final(
    const float* __restrict__ W1, const float* __restrict__ b1,
    const float* __restrict__ W2, const float* __restrict__ b2,
    float* __restrict__ out)
{
    __shared__ float sp[DDIM];
    __shared__ float sh[DDIM];
    __shared__ float red[256];
    int b = blockIdx.x, d = threadIdx.x;
    float m = -FLT_MAX;
    for (int c = 0; c < 8; c++) m = fmaxf(m, g_pmax[(b*8 + c)*DDIM + d]);
    sp[d] = m;
    __syncthreads();
    float a = b1[d];
    for (int k = 0; k < DDIM; k++) a += sp[k]*W1[k*DDIM + d];
    a = fmaxf(a, 0.f);
    sh[d] = a;
    __syncthreads();
    float o = b2[d];
    for (int k = 0; k < DDIM; k++) o += sh[k]*W2[k*DDIM + d];
    o = fmaxf(o, 0.f);
    red[d] = o*o;
    __syncthreads();
    for (int s = 128; s; s >>= 1) { if (d < s) red[d] += red[d + s]; __syncthreads(); }
    float nrm = sqrtf(red[0]);
    out[b*DDIM + d] = o / fmaxf(nrm, 1e-12f);
}

// ---------------- launch ----------------
extern "C" void kernel_launch(void* const* d_in, const int* in_sizes, int n_in,
                              void* d_out, int out_size)
{
    const int*   class_idx   = (const int*)  d_in[0];
    const float* colors      = (const float*)d_in[1];
    const float* positions   = (const float*)d_in[2];
    const float* class_table = (const float*)d_in[3];
    const float* posW1 = (const float*)d_in[4];
    const float* posb1 = (const float*)d_in[5];
    const float* posW2 = (const float*)d_in[6];
    const float* posb2 = (const float*)d_in[7];
    const float* colW1 = (const float*)d_in[8];
    const float* colb1 = (const float*)d_in[9];
    const float* colW2 = (const float*)d_in[10];
    const float* colb2 = (const float*)d_in[11];
    const float* mW    = (const float*)d_in[12];
    const float* mb    = (const float*)d_in[13];
    const float* gW1   = (const float*)d_in[14];
    const float* gb1   = (const float*)d_in[15];
    const float* gg1   = (const float*)d_in[16];
    const float* gbe1  = (const float*)d_in[17];
    const float* gW2   = (const float*)d_in[18];
    const float* gb2   = (const float*)d_in[19];
    const float* gg2   = (const float*)d_in[20];
    const float* gbe2  = (const float*)d_in[21];
    const float* lW1   = (const float*)d_in[22];
    const float* lb1   = (const float*)d_in[23];
    const float* lW2   = (const float*)d_in[24];
    const float* lb2   = (const float*)d_in[25];
    float* out = (float*)d_out;

    static int cfg_done = 0;
    if (!cfg_done) {
        cudaFuncSetAttribute(k2_mma,  cudaFuncAttributeMaxDynamicSharedMemorySize, K2_SMEM_SZ);
        cudaFuncSetAttribute(k3a_mma, cudaFuncAttributeMaxDynamicSharedMemorySize, K3A_SMEM_SZ);
        cudaFuncSetAttribute(k4_mma,  cudaFuncAttributeMaxDynamicSharedMemorySize, K4_SMEM_SZ);
        cfg_done = 1;
    }

    k_prep<<<768, 256>>>(gW1, gW2);
    k1_features<<<NNODE/16, 256>>>(class_idx, colors, positions, class_table,
                                   posW1, posb1, posW2, posb2,
                                   colW1, colb1, colW2, colb2, mW, mb);
    k1b_split<<<NNODE*DDIM/1024, 256>>>();
    dim3 g2(NN/64, BB);
    k2_mma<<<g2, 256, K2_SMEM_SZ>>>();
    dim3 g3(4, NNODE/128);
    k3a_mma<<<g3, 256, K3A_SMEM_SZ>>>(gb1);
    k3b_stats<<<NNODE/16, 256>>>();
    k_finalize<<<1, 256>>>(0, 0, gg1, gbe1);
    k4_mma<<<NNODE/8, 256, K4_SMEM_SZ>>>(gb2);
    k_finalize<<<1, 256>>>(2*DDIM, 2*DDIM, gg2, gbe2);
    dim3 g5(8, BB);
    k5_maxpart<<<g5, 256>>>();
    k6_final<<<BB, 256>>>(lW1, lb1, lW2, lb2, out);
}